// round 5
// baseline (speedup 1.0000x reference)
#include <cuda_runtime.h>
#include <cstdint>

// ---------------------------------------------------------------------------
// minLSTM cell, fused: grouped linears + gate math + scan, f32x2-packed gates.
//
// Shapes: x (B=4, S=8192, D=1024), W* (128 groups, 8, 8), out (4, 8192, 1024).
//
// Exact algebraic rewrite of the reference:
//   F,I,G = grouped 8x8 linears
//   eF=exp(-F), eI=exp(-I), d = 2+eF+eI
//   f = (1+eI)/d * exp(EPS)   (EPS folded from cumsum(log_f + EPS))
//   i = (1+eF)/d
//   g = G>=0 ? G+0.5+1e-8 : sigmoid(G)
//   h_t = f_t * h_{t-1} + i_t * g_t,  h_{-1} = 0
//
// Wf, Wi are pre-scaled by -log2(e) so eF = ex2(dot) directly.
// One CTA per (batch, group-quad) chain of 32 channels; 16 warps = 16 time
// slabs of 8 t each per 128-t iteration; smem double-buffered carry.
// ---------------------------------------------------------------------------

namespace {
constexpr int kS       = 8192;
constexpr int kD       = 1024;
constexpr int kWarps   = 16;
constexpr int kThreads = kWarps * 32;            // 512
constexpr int kTper    = 8;                      // timesteps per thread
constexpr int kIterT   = kWarps * kTper;         // 128 timesteps per iteration
constexpr int kNIter   = kS / kIterT;            // 64
constexpr int kNChain  = 128;                    // 4 batches * 32 group-quads
constexpr float kNegLog2e = -1.4426950408889634f;
}  // namespace

__device__ float g_wf2[128 * 64];                // Wf * -log2(e)
__device__ float g_wi2[128 * 64];                // Wi * -log2(e)

__global__ void prep_kernel(const float* __restrict__ Wf,
                            const float* __restrict__ Wi) {
  int i = blockIdx.x * blockDim.x + threadIdx.x;
  if (i < 128 * 64) {
    g_wf2[i] = Wf[i] * kNegLog2e;
    g_wi2[i] = Wi[i] * kNegLog2e;
  }
}

using ull = unsigned long long;

__device__ __forceinline__ ull pack2(float lo, float hi) {
  ull r;
  asm("mov.b64 %0, {%1, %2};" : "=l"(r) : "f"(lo), "f"(hi));
  return r;
}
__device__ __forceinline__ void unpack2(ull p, float& lo, float& hi) {
  asm("mov.b64 {%0, %1}, %2;" : "=f"(lo), "=f"(hi) : "l"(p));
}
__device__ __forceinline__ ull fma2(ull a, ull b, ull c) {
  ull d;
  asm("fma.rn.f32x2 %0, %1, %2, %3;" : "=l"(d) : "l"(a), "l"(b), "l"(c));
  return d;
}
__device__ __forceinline__ ull mul2(ull a, ull b) {
  ull d;
  asm("mul.rn.f32x2 %0, %1, %2;" : "=l"(d) : "l"(a), "l"(b));
  return d;
}
__device__ __forceinline__ float ex2f(float x) {
  float r;
  asm("ex2.approx.f32 %0, %1;" : "=f"(r) : "f"(x));
  return r;
}
__device__ __forceinline__ float frcp(float x) {
  float r;
  asm("rcp.approx.f32 %0, %1;" : "=f"(r) : "f"(x));
  return r;
}

// From pre-scaled dots Fd=-F*log2e, Id=-I*log2e and raw G -> (f, v).
__device__ __forceinline__ void gate_tail(float Fd, float Id, float G,
                                          float& f, float& v) {
  const float eF = ex2f(Fd);                     // e^{-F}
  const float eI = ex2f(Id);                     // e^{-I}
  const float eG = ex2f(G * kNegLog2e);          // e^{-G}
  const float g1 = 1.f + eG;
  const float s  = 2.f + eF + eI;
  const float r  = frcp(s * g1);                 // one MUFU for two divisions
  const float inv_s = g1 * r;                    // 1/s
  const float f0 = fmaf(eI, inv_s, inv_s);       // (1+eI)/s
  f = fmaf(f0, 1e-8f, f0);                       // * exp(EPS) from cumsum
  const float ic = fmaf(eF, inv_s, inv_s);       // (1+eF)/s
  const float g  = (G >= 0.f) ? (G + 0.5f + 1e-8f) : (s * r);  // s*r = sigmoid(G)
  v = ic * g;
}

__global__ __launch_bounds__(kThreads, 1) void minlstm_kernel(
    const float* __restrict__ x, const float* __restrict__ Wh,
    float* __restrict__ out) {
  const int chain = blockIdx.x;                  // 0..127
  const int b     = chain >> 5;
  const int gq    = chain & 31;                  // group-quad (4 groups, 32 ch)
  const int w     = threadIdx.x >> 5;            // warp = time slab
  const int c     = threadIdx.x & 31;            // lane = channel

  // Packed-duplicated per-channel weight rows (lane-broadcast within group).
  const int row = gq * 32 + c;
  ull wfp[8], wip[8], whp[8];
#pragma unroll
  for (int k = 0; k < 8; k++) {
    const float wf = g_wf2[row * 8 + k];
    const float wi = g_wi2[row * 8 + k];
    const float wh = Wh[row * 8 + k];
    wfp[k] = pack2(wf, wf);
    wip[k] = pack2(wi, wi);
    whp[k] = pack2(wh, wh);
  }

  __shared__ float2 sc[kWarps][32];
  __shared__ float  Hs[2][32];
  if (threadIdx.x < 32) { Hs[0][c] = 0.f; Hs[1][c] = 0.f; }

  const float* xbase = x + (size_t)b * kS * kD + gq * 32 + (c & 24);
  float* obase       = out + (size_t)b * kS * kD + gq * 32 + c;

  for (int iter = 0; iter < kNIter; iter++) {
    const int t0 = iter * kIterT + w * kTper;
    const float* xp = xbase + (size_t)t0 * kD;

    float aj[kTper], bj[kTper];
    float A = 1.f, Bv = 0.f;                     // running affine for this slab
#pragma unroll
    for (int j = 0; j < kTper; j += 2) {
      const float4 a0 = *reinterpret_cast<const float4*>(xp + (size_t)j * kD);
      const float4 b0 = *reinterpret_cast<const float4*>(xp + (size_t)j * kD + 4);
      const float4 a1 = *reinterpret_cast<const float4*>(xp + (size_t)(j + 1) * kD);
      const float4 b1 = *reinterpret_cast<const float4*>(xp + (size_t)(j + 1) * kD + 4);

      const ull p0 = pack2(a0.x, a1.x), p1 = pack2(a0.y, a1.y);
      const ull p2 = pack2(a0.z, a1.z), p3 = pack2(a0.w, a1.w);
      const ull p4 = pack2(b0.x, b1.x), p5 = pack2(b0.y, b1.y);
      const ull p6 = pack2(b0.z, b1.z), p7 = pack2(b0.w, b1.w);

      ull F2 = mul2(p0, wfp[0]);
      F2 = fma2(p1, wfp[1], F2); F2 = fma2(p2, wfp[2], F2);
      F2 = fma2(p3, wfp[3], F2); F2 = fma2(p4, wfp[4], F2);
      F2 = fma2(p5, wfp[5], F2); F2 = fma2(p6, wfp[6], F2);
      F2 = fma2(p7, wfp[7], F2);

      ull I2 = mul2(p0, wip[0]);
      I2 = fma2(p1, wip[1], I2); I2 = fma2(p2, wip[2], I2);
      I2 = fma2(p3, wip[3], I2); I2 = fma2(p4, wip[4], I2);
      I2 = fma2(p5, wip[5], I2); I2 = fma2(p6, wip[6], I2);
      I2 = fma2(p7, wip[7], I2);

      ull G2 = mul2(p0, whp[0]);
      G2 = fma2(p1, whp[1], G2); G2 = fma2(p2, whp[2], G2);
      G2 = fma2(p3, whp[3], G2); G2 = fma2(p4, whp[4], G2);
      G2 = fma2(p5, whp[5], G2); G2 = fma2(p6, whp[6], G2);
      G2 = fma2(p7, whp[7], G2);

      float Fa, Fb, Ia, Ib, Ga, Gb;
      unpack2(F2, Fa, Fb);
      unpack2(I2, Ia, Ib);
      unpack2(G2, Ga, Gb);

      float f, v;
      gate_tail(Fa, Ia, Ga, f, v);
      aj[j] = f; bj[j] = v;
      A *= f; Bv = fmaf(f, Bv, v);

      gate_tail(Fb, Ib, Gb, f, v);
      aj[j + 1] = f; bj[j + 1] = v;
      A *= f; Bv = fmaf(f, Bv, v);
    }

    sc[w][c] = make_float2(A, Bv);
    __syncthreads();                             // sc visible; Hs[buf] stable

    // Exclusive prefix over earlier slabs for this channel.
    float Ae = 1.f, Be = 0.f;
    for (int k = 0; k < w; k++) {
      const float2 p = sc[k][c];
      Be = fmaf(p.x, Be, p.y);
      Ae *= p.x;
    }

    const float Hp = Hs[iter & 1][c];            // carry entering this iteration

    // Last slab publishes next carry into the other buffer (readers sync at
    // the next iteration's __syncthreads()).
    if (w == kWarps - 1) {
      Hs[(iter + 1) & 1][c] = fmaf(A * Ae, Hp, fmaf(A, Be, Bv));
    }

    // Apply carry and emit; lanes are 32 contiguous floats -> coalesced 128B.
    float h = fmaf(Ae, Hp, Be);
    float* op = obase + (size_t)t0 * kD;
#pragma unroll
    for (int j = 0; j < kTper; j++) {
      h = fmaf(aj[j], h, bj[j]);
      op[(size_t)j * kD] = h;
    }
  }
}

extern "C" void kernel_launch(void* const* d_in, const int* in_sizes, int n_in,
                              void* d_out, int out_size) {
  (void)in_sizes; (void)n_in; (void)out_size;
  const float* x  = (const float*)d_in[0];
  const float* Wf = (const float*)d_in[1];
  const float* Wi = (const float*)d_in[2];
  const float* Wh = (const float*)d_in[3];
  float* out = (float*)d_out;

  prep_kernel<<<32, 256>>>(Wf, Wi);
  minlstm_kernel<<<kNChain, kThreads>>>(x, Wh, out);
}